// round 13
// baseline (speedup 1.0000x reference)
#include <cuda_runtime.h>

#define Hd 256
#define Bb 32
#define Ss 48
#define Tt 48
#define NGRP 37   // 148 CTAs / 4 j-blocks

// Scratch (device globals: no allocation allowed)
__device__ float g_XW0[Ss * Bb * Hd];          // src[s] @ W0
__device__ float g_YW0[Tt * Bb * Hd];          // trg[t] @ W0
__device__ float g_XW1[Ss * Tt * Bb * Hd];     // HX0[s,t] @ W1   (72 MB), filled by chase
__device__ float g_YW1[Ss * Tt * Bb * Hd];     // HY0[s,t] @ W1   (72 MB), filled by chase
__device__ float g_UI[2 * Hd * Hd * 2];        // interleaved (Ux[i][j], Uy[i][j]) per layer
__device__ float g_W1T[Hd * Hd];               // W1 transposed: g_W1T[j][i] = W1[i][j]
__device__ int   g_flag[2 * Ss * Tt];          // per-cell completion counters (4 = done)
__device__ float g_zero[Bb * Hd];              // stays 0 (zero-init, never written)

// ---- packed fp32x2 helpers (ptxas will not auto-emit FFMA2 from C++) ----
__device__ __forceinline__ void fma2(unsigned long long& d, unsigned long long a, unsigned long long b) {
    asm("fma.rn.f32x2 %0, %1, %2, %0;" : "+l"(d) : "l"(a), "l"(b));
}
__device__ __forceinline__ unsigned long long dup2(float x) {
    unsigned long long r; asm("mov.b64 %0, {%1, %1};" : "=l"(r) : "f"(x)); return r;
}
__device__ __forceinline__ unsigned long long pk2(float a, float b) {
    unsigned long long r; asm("mov.b64 %0, {%1, %2};" : "=l"(r) : "f"(a), "f"(b)); return r;
}
__device__ __forceinline__ float2 unpk(unsigned long long v) {
    float2 f; asm("mov.b64 {%0, %1}, %2;" : "=f"(f.x), "=f"(f.y) : "l"(v)); return f;
}
__device__ __forceinline__ int ld_acq(const int* p) {
    int v; asm volatile("ld.acquire.gpu.global.b32 %0, [%1];" : "=r"(v) : "l"(p) : "memory"); return v;
}
__device__ __forceinline__ void red_release(int* p) {
    asm volatile("red.release.gpu.global.add.u32 [%0], %1;" :: "l"(p), "r"(1) : "memory");
}
// HW tanh: MUFU.TANH, 1 instruction (max rel err ~1e-4 pointwise, budget 1e-3)
__device__ __forceinline__ float ftanh(float x) {
    float r; asm("tanh.approx.f32 %0, %1;" : "=f"(r) : "f"(x)); return r;
}

__global__ void zero_flags() {
    int i = blockIdx.x * 512 + threadIdx.x;
    if (i < 2 * Ss * Tt) g_flag[i] = 0;
}

// ---- build interleaved (Ux, Uy) pairs + transposed W1 ----
__global__ void k_interleave(const float* __restrict__ U, const float* __restrict__ W) {
    int idx = blockIdx.x * 256 + threadIdx.x;      // 0 .. 196607
    if (idx < 131072) {
        int d = idx >> 16;
        int r = idx & 0xFFFF;                      // i*256 + j
        const float* Ud = U + d * 2 * Hd * Hd;
        float ux = Ud[r];
        float uy = Ud[Hd * Hd + r];
        reinterpret_cast<float2*>(g_UI)[idx] = make_float2(ux, uy);
    } else {
        int r = idx - 131072;                      // 0 .. 65535
        int i = r >> 8, j = r & 255;               // consecutive threads -> consecutive j (coalesced read)
        g_W1T[j * Hd + i] = W[Hd * Hd + i * Hd + j];
    }
}

// ---- layer-0 input GEMM: C[g] = A[g] @ W0. One CTA does all 4 j-blocks ----
__global__ void __launch_bounds__(128) pre_kernel(const float* __restrict__ Ax,
                                                  const float* __restrict__ Ay,
                                                  int gstride,
                                                  const float* __restrict__ Wm) {
    __shared__ float smf[16 * 258 * 2];            // b-pairs interleaved, padded stride
    int z = blockIdx.y;
    const float* A = z ? Ay : Ax;
    float* C = z ? g_YW0 : g_XW0;

    int g = blockIdx.x, tid = threadIdx.x;
    const float* Ag = A + (size_t)g * gstride;
    for (int idx = tid; idx < Bb * Hd; idx += 128) {
        int b = idx >> 8, i = idx & 255;
        smf[((b >> 1) * 258 + i) * 2 + (b & 1)] = Ag[idx];
    }
    __syncthreads();

    const unsigned long long* sm64 = reinterpret_cast<const unsigned long long*>(smf);
    int jq = tid & 15, bq = tid >> 4;
    const unsigned long long* mp0 = sm64 + (bq * 2) * 258;
    const unsigned long long* mp1 = sm64 + (bq * 2 + 1) * 258;
    float* Cg = C + (size_t)g * (Bb * Hd);
    int b0 = bq * 4;

    for (int jb = 0; jb < 4; jb++) {
        int j0 = jb * 64 + jq * 4;
        unsigned long long a00 = 0, a01 = 0, a02 = 0, a03 = 0;
        unsigned long long a10 = 0, a11 = 0, a12 = 0, a13 = 0;
        const float4* Wr = reinterpret_cast<const float4*>(Wm + j0);

#pragma unroll 8
        for (int i = 0; i < 256; i++) {
            float4 w = Wr[i * 64];
            unsigned long long w0 = dup2(w.x), w1 = dup2(w.y), w2 = dup2(w.z), w3 = dup2(w.w);
            unsigned long long m0 = mp0[i], m1 = mp1[i];
            fma2(a00, m0, w0); fma2(a01, m0, w1); fma2(a02, m0, w2); fma2(a03, m0, w3);
            fma2(a10, m1, w0); fma2(a11, m1, w1); fma2(a12, m1, w2); fma2(a13, m1, w3);
        }

        float2 r00 = unpk(a00), r01 = unpk(a01), r02 = unpk(a02), r03 = unpk(a03);
        float2 r10 = unpk(a10), r11 = unpk(a11), r12 = unpk(a12), r13 = unpk(a13);
        *reinterpret_cast<float4*>(&Cg[(b0 + 0) * Hd + j0]) = make_float4(r00.x, r01.x, r02.x, r03.x);
        *reinterpret_cast<float4*>(&Cg[(b0 + 1) * Hd + j0]) = make_float4(r00.y, r01.y, r02.y, r03.y);
        *reinterpret_cast<float4*>(&Cg[(b0 + 2) * Hd + j0]) = make_float4(r10.x, r11.x, r12.x, r13.x);
        *reinterpret_cast<float4*>(&Cg[(b0 + 3) * Hd + j0]) = make_float4(r10.y, r11.y, r12.y, r13.y);
    }
}

// ---- chase: compute XW1/YW1 slice (64 j-cols) for a finished layer-0 cell ----
// Per thread: 2 b-rows x 4 j-cols, (x,y) packed as f32x2. Operands from L2.
__device__ __forceinline__ void chase_cell(int gc, int j0, int b0, const float* __restrict__ out) {
    const float* hx = out + (size_t)gc * 2 * (Bb * Hd);
    const float* hy = hx + Bb * Hd;
    unsigned long long cacc[2][4] = {};

#pragma unroll 2
    for (int i = 0; i < 256; i += 4) {
        float4 x0 = *reinterpret_cast<const float4*>(&hx[(b0 + 0) * Hd + i]);
        float4 x1 = *reinterpret_cast<const float4*>(&hx[(b0 + 1) * Hd + i]);
        float4 y0 = *reinterpret_cast<const float4*>(&hy[(b0 + 0) * Hd + i]);
        float4 y1 = *reinterpret_cast<const float4*>(&hy[(b0 + 1) * Hd + i]);
        unsigned long long p00 = pk2(x0.x, y0.x), p01 = pk2(x0.y, y0.y);
        unsigned long long p02 = pk2(x0.z, y0.z), p03 = pk2(x0.w, y0.w);
        unsigned long long p10 = pk2(x1.x, y1.x), p11 = pk2(x1.y, y1.y);
        unsigned long long p12 = pk2(x1.z, y1.z), p13 = pk2(x1.w, y1.w);
#pragma unroll
        for (int jj = 0; jj < 4; jj++) {
            float4 w = *reinterpret_cast<const float4*>(&g_W1T[(j0 + jj) * Hd + i]);
            unsigned long long w0 = dup2(w.x), w1 = dup2(w.y), w2 = dup2(w.z), w3 = dup2(w.w);
            fma2(cacc[0][jj], p00, w0); fma2(cacc[0][jj], p01, w1);
            fma2(cacc[0][jj], p02, w2); fma2(cacc[0][jj], p03, w3);
            fma2(cacc[1][jj], p10, w0); fma2(cacc[1][jj], p11, w1);
            fma2(cacc[1][jj], p12, w2); fma2(cacc[1][jj], p13, w3);
        }
    }

    size_t base = (size_t)gc * (Bb * Hd);
#pragma unroll
    for (int b = 0; b < 2; b++) {
        float2 c0 = unpk(cacc[b][0]), c1 = unpk(cacc[b][1]);
        float2 c2 = unpk(cacc[b][2]), c3 = unpk(cacc[b][3]);
        *reinterpret_cast<float4*>(&g_XW1[base + (b0 + b) * Hd + j0]) = make_float4(c0.x, c1.x, c2.x, c3.x);
        *reinterpret_cast<float4*>(&g_YW1[base + (b0 + b) * Hd + j0]) = make_float4(c0.y, c1.y, c2.y, c3.y);
    }
}

// ---- persistent wavefront kernel: one layer per launch ----
// Grid = 148 CTAs, 256 threads (8 warps, 2/SMSP). CTA (grp, jb).
// Layer 0 also "chases": after releasing cell n, computes pre1 (XW1/YW1 slice)
// for its own cell n-2, hiding that work inside the wavefront sync latency.
__global__ void __launch_bounds__(256, 1) wave_kernel(float* __restrict__ out,
                                                      const float* __restrict__ bias,
                                                      int layer) {
    extern __shared__ float sm[];
    // [0, 131072): weight chunks ws[256][32] of 16B (de-interleaved even/odd slots)
    // [131072, 197120): parent tile smf[32][258][2] floats
    ulonglong2* ws = reinterpret_cast<ulonglong2*>(sm);
    float* smf = sm + 32768;

    int tid = threadIdx.x;
    int jb = blockIdx.x & 3, grp = blockIdx.x >> 2;
    int j0base = jb * 64;

    // Stage this CTA's 128KB weight tile once
    {
        const ulonglong2* UI2 = reinterpret_cast<const ulonglong2*>(g_UI) + layer * 32768 + (j0base >> 1);
        for (int idx = tid; idx < 8192; idx += 256) {
            int i = idx >> 5, q = idx & 31;
            int slot = ((q & 1) << 4) | (q >> 1);
            ws[i * 32 + slot] = UI2[i * 128 + q];
        }
    }
    __syncthreads();

    // Thread decomposition: warp = (jhalf, bgroup); lane = (bsub, jql)
    int w = tid >> 5, lane = tid & 31;
    int jhalf = w & 1, bgroup = w >> 1;            // bgroup 0..3 -> 8 b-rows
    int jql = lane & 7, bsub = lane >> 3;          // bsub 0..3 -> 2 b-rows
    int jq = jhalf * 8 + jql;
    int j0 = j0base + jq * 4;
    int b0 = bgroup * 8 + bsub * 2;                // rows b0, b0+1
    (void)lane;

    float4 bv = *reinterpret_cast<const float4*>(&bias[layer * Hd + j0]);

    const unsigned long long* sm64 = reinterpret_cast<const unsigned long long*>(smf);
    const unsigned long long* m0p = sm64 + b0 * 258;
    const unsigned long long* m1p = m0p + 258;

    int flg_base = layer * (Ss * Tt);
    int prev1 = -1, prev2 = -1;                    // chase queue (layer 0 only)

    for (int k = 0; k < Ss + Tt - 1; k++) {
        int s_lo = (k > Tt - 1) ? (k - (Tt - 1)) : 0;
        int s_hi = (k < Ss - 1) ? k : (Ss - 1);
        int wdt = s_hi - s_lo + 1;

        for (int c = grp; c < wdt; c += NGRP) {
            int s = s_lo + c;
            int t = k - s;
            int cell = s * Tt + t;

            // Prefetch epilogue operands (independent of parents)
            const float* xw;
            const float* yw;
            if (layer == 0) {
                xw = g_XW0 + s * (Bb * Hd);
                yw = g_YW0 + t * (Bb * Hd);
            } else {
                int gc = s * Tt + t;
                xw = g_XW1 + (size_t)gc * (Bb * Hd);
                yw = g_YW1 + (size_t)gc * (Bb * Hd);
            }
            float4 xv0 = *reinterpret_cast<const float4*>(&xw[(b0 + 0) * Hd + j0]);
            float4 xv1 = *reinterpret_cast<const float4*>(&xw[(b0 + 1) * Hd + j0]);
            float4 yv0 = *reinterpret_cast<const float4*>(&yw[(b0 + 0) * Hd + j0]);
            float4 yv1 = *reinterpret_cast<const float4*>(&yw[(b0 + 1) * Hd + j0]);

            // Wait for both parents: 2 lanes poll, barrier-broadcast (R8 scheme)
            if (tid < 2) {
                const int* f = nullptr;
                if (tid == 0 && s > 0) f = &g_flag[flg_base + cell - Tt];
                if (tid == 1 && t > 0) f = &g_flag[flg_base + cell - 1];
                if (f) while (ld_acq(f) < 4) __nanosleep(40);
            }
            __syncthreads();

            // Stage parent h_x tiles interleaved (up, left); branchless via g_zero
            const float* up = (s > 0) ? out + (size_t)((layer * Ss + s - 1) * Tt + t) * 2 * (Bb * Hd) : g_zero;
            const float* lf = (t > 0) ? out + (size_t)((layer * Ss + s) * Tt + t - 1) * 2 * (Bb * Hd) : g_zero;
            for (int idx = tid; idx < 2048; idx += 256) {
                int b = idx >> 6, i4 = (idx & 63) << 2;
                float4 u = *reinterpret_cast<const float4*>(&up[b * Hd + i4]);
                float4 l = *reinterpret_cast<const float4*>(&lf[b * Hd + i4]);
                float4* dst = reinterpret_cast<float4*>(&smf[(b * 258 + i4) * 2]);
                dst[0] = make_float4(u.x, l.x, u.y, l.y);
                dst[1] = make_float4(u.z, l.z, u.w, l.w);
            }
            __syncthreads();

            // Recurrent GEMM: acc.lo = up@Ux, acc.hi = left@Uy (all operands in smem).
            unsigned long long acc[2][4] = {};
#pragma unroll 2
            for (int i = 0; i < 256; i += 2) {
                ulonglong2 m0 = *reinterpret_cast<const ulonglong2*>(m0p + i);
                ulonglong2 m1 = *reinterpret_cast<const ulonglong2*>(m1p + i);
                ulonglong2 wA0 = ws[i * 32 + jq];
                ulonglong2 wB0 = ws[i * 32 + 16 + jq];
                ulonglong2 wA1 = ws[(i + 1) * 32 + jq];
                ulonglong2 wB1 = ws[(i + 1) * 32 + 16 + jq];
                fma2(acc[0][0], m0.x, wA0.x); fma2(acc[0][1], m0.x, wA0.y);
                fma2(acc[0][2], m0.x, wB0.x); fma2(acc[0][3], m0.x, wB0.y);
                fma2(acc[1][0], m1.x, wA0.x); fma2(acc[1][1], m1.x, wA0.y);
                fma2(acc[1][2], m1.x, wB0.x); fma2(acc[1][3], m1.x, wB0.y);
                fma2(acc[0][0], m0.y, wA1.x); fma2(acc[0][1], m0.y, wA1.y);
                fma2(acc[0][2], m0.y, wB1.x); fma2(acc[0][3], m0.y, wB1.y);
                fma2(acc[1][0], m1.y, wA1.x); fma2(acc[1][1], m1.y, wA1.y);
                fma2(acc[1][2], m1.y, wB1.x); fma2(acc[1][3], m1.y, wB1.y);
            }

            // Epilogue
            float* outc = out + (size_t)((layer * Ss + s) * Tt + t) * 2 * (Bb * Hd);
            float bja[4] = {bv.x, bv.y, bv.z, bv.w};
            {
                float tmp0[4], tmp1[4];
#pragma unroll
                for (int jj = 0; jj < 4; jj++) {
                    float2 p0 = unpk(acc[0][jj]);
                    float2 p1 = unpk(acc[1][jj]);
                    tmp0[jj] = p0.x + p0.y + bja[jj];
                    tmp1[jj] = p1.x + p1.y + bja[jj];
                }
                float4 ox0 = make_float4(ftanh(xv0.x + tmp0[0]), ftanh(xv0.y + tmp0[1]),
                                         ftanh(xv0.z + tmp0[2]), ftanh(xv0.w + tmp0[3]));
                float4 oy0 = make_float4(ftanh(yv0.x + tmp0[0]), ftanh(yv0.y + tmp0[1]),
                                         ftanh(yv0.z + tmp0[2]), ftanh(yv0.w + tmp0[3]));
                float4 ox1 = make_float4(ftanh(xv1.x + tmp1[0]), ftanh(xv1.y + tmp1[1]),
                                         ftanh(xv1.z + tmp1[2]), ftanh(xv1.w + tmp1[3]));
                float4 oy1 = make_float4(ftanh(yv1.x + tmp1[0]), ftanh(yv1.y + tmp1[1]),
                                         ftanh(yv1.z + tmp1[2]), ftanh(yv1.w + tmp1[3]));
                *reinterpret_cast<float4*>(&outc[(b0 + 0) * Hd + j0]) = ox0;              // h_x
                *reinterpret_cast<float4*>(&outc[(b0 + 1) * Hd + j0]) = ox1;
                *reinterpret_cast<float4*>(&outc[Bb * Hd + (b0 + 0) * Hd + j0]) = oy0;    // h_y
                *reinterpret_cast<float4*>(&outc[Bb * Hd + (b0 + 1) * Hd + j0]) = oy1;
            }

            // Publish: bar orders every thread's STGs; single release per CTA.
            __syncthreads();
            if (tid == 0) red_release(&g_flag[flg_base + cell]);

            // Chase (layer 0): pre1 for our cell from 2 links back — hidden in
            // the sync-latency window before the next link's parents are needed.
            if (layer == 0) {
                if (prev2 >= 0) {
                    const int* f = &g_flag[prev2];
                    while (ld_acq(f) < 4) __nanosleep(40);
                    chase_cell(prev2, j0, b0, out);
                }
                prev2 = prev1;
                prev1 = cell;
            }
        }
    }

    // Tail: finish the last two chases
    if (layer == 0) {
        if (prev2 >= 0) {
            const int* f = &g_flag[prev2];
            while (ld_acq(f) < 4) __nanosleep(40);
            chase_cell(prev2, j0, b0, out);
        }
        if (prev1 >= 0) {
            const int* f = &g_flag[prev1];
            while (ld_acq(f) < 4) __nanosleep(40);
            chase_cell(prev1, j0, b0, out);
        }
    }
}

extern "C" void kernel_launch(void* const* d_in, const int* in_sizes, int n_in,
                              void* d_out, int out_size) {
    const float* src  = (const float*)d_in[0];   // (48, 32, 256)
    const float* trg  = (const float*)d_in[1];   // (48, 32, 256)
    const float* W    = (const float*)d_in[2];   // (2, 256, 256)
    const float* U    = (const float*)d_in[3];   // (2, 512, 256)
    const float* bias = (const float*)d_in[4];   // (2, 1, 256)
    float* out = (float*)d_out;                  // (2, 48, 48, 2, 32, 256)

    static const int WAVE_SMEM = 131072 + 16 * 258 * 2 * 2 * 4;  // 197120
    cudaFuncSetAttribute(wave_kernel, cudaFuncAttributeMaxDynamicSharedMemorySize, WAVE_SMEM);

    zero_flags<<<9, 512>>>();
    k_interleave<<<768, 256>>>(U, W);

    // Layer-0 input GEMMs (x and y merged via grid.y)
    pre_kernel<<<dim3(48, 2), 128>>>(src, trg, Bb * Hd, W);

    // Layer-0 wavefront (persistent) + embedded pre1 chase
    wave_kernel<<<148, 256, WAVE_SMEM>>>(out, bias, 0);

    // Layer-1 wavefront (persistent) — XW1/YW1 were produced by the chase
    wave_kernel<<<148, 256, WAVE_SMEM>>>(out, bias, 1);
}

// round 15
// speedup vs baseline: 2.1100x; 2.1100x over previous
#include <cuda_runtime.h>

#define Hd 256
#define Bb 32
#define Ss 48
#define Tt 48
#define NGRP 37   // 148 CTAs / 4 j-blocks

// Scratch (device globals: no allocation allowed)
__device__ float g_XW0[Ss * Bb * Hd];          // src[s] @ W0
__device__ float g_YW0[Tt * Bb * Hd];          // trg[t] @ W0
__device__ float g_XW1[Ss * Tt * Bb * Hd];     // HX0[s,t] @ W1   (72 MB)
__device__ float g_YW1[Ss * Tt * Bb * Hd];     // HY0[s,t] @ W1   (72 MB)
__device__ float g_UI[2 * Hd * Hd * 2];        // interleaved (Ux[i][j], Uy[i][j]) per layer
__device__ int   g_flag[2 * Ss * Tt];          // per-cell completion counters (4 = done)
__device__ float g_zero[Bb * Hd];              // stays 0 (zero-init, never written)

// ---- packed fp32x2 helpers (ptxas will not auto-emit FFMA2 from C++) ----
__device__ __forceinline__ void fma2(unsigned long long& d, unsigned long long a, unsigned long long b) {
    asm("fma.rn.f32x2 %0, %1, %2, %0;" : "+l"(d) : "l"(a), "l"(b));
}
__device__ __forceinline__ unsigned long long dup2(float x) {
    unsigned long long r; asm("mov.b64 %0, {%1, %1};" : "=l"(r) : "f"(x)); return r;
}
__device__ __forceinline__ float2 unpk(unsigned long long v) {
    float2 f; asm("mov.b64 {%0, %1}, %2;" : "=f"(f.x), "=f"(f.y) : "l"(v)); return f;
}
__device__ __forceinline__ int ld_acq(const int* p) {
    int v; asm volatile("ld.acquire.gpu.global.b32 %0, [%1];" : "=r"(v) : "l"(p) : "memory"); return v;
}
__device__ __forceinline__ void red_release(int* p) {
    asm volatile("red.release.gpu.global.add.u32 [%0], %1;" :: "l"(p), "r"(1) : "memory");
}
// HW tanh: MUFU.TANH, 1 instruction (pointwise rel err ~1e-4, budget 1e-3)
__device__ __forceinline__ float ftanh(float x) {
    float r; asm("tanh.approx.f32 %0, %1;" : "=f"(r) : "f"(x)); return r;
}

__global__ void zero_flags() {
    int i = blockIdx.x * 512 + threadIdx.x;
    if (i < 2 * Ss * Tt) g_flag[i] = 0;
}

// ---- build interleaved (Ux, Uy) pairs: g_UI[layer][i][j] = {Ux[i][j], Uy[i][j]} ----
__global__ void k_interleave(const float* __restrict__ U) {
    int idx = blockIdx.x * 256 + threadIdx.x;      // 0 .. 2*65536-1
    int d = idx >> 16;
    int r = idx & 0xFFFF;                          // i*256 + j
    const float* Ud = U + d * 2 * Hd * Hd;
    float ux = Ud[r];
    float uy = Ud[Hd * Hd + r];
    reinterpret_cast<float2*>(g_UI)[idx] = make_float2(ux, uy);
}

// ---- batched GEMM: C[g] = A[g] @ Wm. One CTA does ALL 4 j-blocks (A staged once) ----
__global__ void __launch_bounds__(128) pre_kernel(const float* __restrict__ Ax,
                                                  const float* __restrict__ Ay,
                                                  int gstride,
                                                  const float* __restrict__ Wm, int mode) {
    __shared__ float smf[16 * 258 * 2];            // b-pairs interleaved, padded stride
    int z = blockIdx.y;
    const float* A = z ? Ay : Ax;
    float* C = (mode == 0) ? (z ? g_YW0 : g_XW0) : (z ? g_YW1 : g_XW1);

    int g = blockIdx.x, tid = threadIdx.x;
    const float* Ag = A + (size_t)g * gstride;
    for (int idx = tid; idx < Bb * Hd; idx += 128) {
        int b = idx >> 8, i = idx & 255;
        smf[((b >> 1) * 258 + i) * 2 + (b & 1)] = Ag[idx];
    }
    __syncthreads();

    const unsigned long long* sm64 = reinterpret_cast<const unsigned long long*>(smf);
    int jq = tid & 15, bq = tid >> 4;
    const unsigned long long* mp0 = sm64 + (bq * 2) * 258;
    const unsigned long long* mp1 = sm64 + (bq * 2 + 1) * 258;
    float* Cg = C + (size_t)g * (Bb * Hd);
    int b0 = bq * 4;

    for (int jb = 0; jb < 4; jb++) {
        int j0 = jb * 64 + jq * 4;
        unsigned long long a00 = 0, a01 = 0, a02 = 0, a03 = 0;
        unsigned long long a10 = 0, a11 = 0, a12 = 0, a13 = 0;
        const float4* Wr = reinterpret_cast<const float4*>(Wm + j0);

#pragma unroll 8
        for (int i = 0; i < 256; i++) {
            float4 w = Wr[i * 64];
            unsigned long long w0 = dup2(w.x), w1 = dup2(w.y), w2 = dup2(w.z), w3 = dup2(w.w);
            unsigned long long m0 = mp0[i], m1 = mp1[i];
            fma2(a00, m0, w0); fma2(a01, m0, w1); fma2(a02, m0, w2); fma2(a03, m0, w3);
            fma2(a10, m1, w0); fma2(a11, m1, w1); fma2(a12, m1, w2); fma2(a13, m1, w3);
        }

        float2 r00 = unpk(a00), r01 = unpk(a01), r02 = unpk(a02), r03 = unpk(a03);
        float2 r10 = unpk(a10), r11 = unpk(a11), r12 = unpk(a12), r13 = unpk(a13);
        *reinterpret_cast<float4*>(&Cg[(b0 + 0) * Hd + j0]) = make_float4(r00.x, r01.x, r02.x, r03.x);
        *reinterpret_cast<float4*>(&Cg[(b0 + 1) * Hd + j0]) = make_float4(r00.y, r01.y, r02.y, r03.y);
        *reinterpret_cast<float4*>(&Cg[(b0 + 2) * Hd + j0]) = make_float4(r10.x, r11.x, r12.x, r13.x);
        *reinterpret_cast<float4*>(&Cg[(b0 + 3) * Hd + j0]) = make_float4(r10.y, r11.y, r12.y, r13.y);
    }
}

// ---- persistent wavefront kernel: one layer per launch ----
// Grid = 148 CTAs, 256 threads (8 warps, 2/SMSP). CTA (grp, jb).
__global__ void __launch_bounds__(256, 1) wave_kernel(float* __restrict__ out,
                                                      const float* __restrict__ bias,
                                                      int layer) {
    extern __shared__ float sm[];
    // [0, 131072): weight chunks ws[256][32] of 16B (de-interleaved even/odd slots)
    // [131072, 197120): parent tile smf[32][258][2] floats
    ulonglong2* ws = reinterpret_cast<ulonglong2*>(sm);
    float* smf = sm + 32768;

    int tid = threadIdx.x;
    int jb = blockIdx.x & 3, grp = blockIdx.x >> 2;
    int j0base = jb * 64;

    // Stage this CTA's 128KB weight tile once
    {
        const ulonglong2* UI2 = reinterpret_cast<const ulonglong2*>(g_UI) + layer * 32768 + (j0base >> 1);
        for (int idx = tid; idx < 8192; idx += 256) {
            int i = idx >> 5, q = idx & 31;
            int slot = ((q & 1) << 4) | (q >> 1);
            ws[i * 32 + slot] = UI2[i * 128 + q];
        }
    }
    __syncthreads();

    // Thread decomposition: warp = (jhalf, bgroup); lane = (bsub, jql)
    int w = tid >> 5, lane = tid & 31;
    int jhalf = w & 1, bgroup = w >> 1;            // bgroup 0..3 -> 8 b-rows
    int jql = lane & 7, bsub = lane >> 3;          // bsub 0..3 -> 2 b-rows
    int jq = jhalf * 8 + jql;
    int j0 = j0base + jq * 4;
    int b0 = bgroup * 8 + bsub * 2;                // rows b0, b0+1
    (void)lane;

    float4 bv = *reinterpret_cast<const float4*>(&bias[layer * Hd + j0]);

    const unsigned long long* sm64 = reinterpret_cast<const unsigned long long*>(smf);
    const unsigned long long* m0p = sm64 + b0 * 258;
    const unsigned long long* m1p = m0p + 258;

    int flg_base = layer * (Ss * Tt);

    for (int k = 0; k < Ss + Tt - 1; k++) {
        int s_lo = (k > Tt - 1) ? (k - (Tt - 1)) : 0;
        int s_hi = (k < Ss - 1) ? k : (Ss - 1);
        int wdt = s_hi - s_lo + 1;

        for (int c = grp; c < wdt; c += NGRP) {
            int s = s_lo + c;
            int t = k - s;
            int cell = s * Tt + t;

            // Prefetch epilogue operands (independent of parents)
            const float* xw;
            const float* yw;
            if (layer == 0) {
                xw = g_XW0 + s * (Bb * Hd);
                yw = g_YW0 + t * (Bb * Hd);
            } else {
                int gc = s * Tt + t;
                xw = g_XW1 + (size_t)gc * (Bb * Hd);
                yw = g_YW1 + (size_t)gc * (Bb * Hd);
            }
            float4 xv0 = *reinterpret_cast<const float4*>(&xw[(b0 + 0) * Hd + j0]);
            float4 xv1 = *reinterpret_cast<const float4*>(&xw[(b0 + 1) * Hd + j0]);
            float4 yv0 = *reinterpret_cast<const float4*>(&yw[(b0 + 0) * Hd + j0]);
            float4 yv1 = *reinterpret_cast<const float4*>(&yw[(b0 + 1) * Hd + j0]);

            // Wait for both parents: 2 lanes spin tight (no sleep), barrier-broadcast.
            // Only 2 pollers per CTA -> minimal LTS pressure on the flag lines,
            // and no nanosleep wakeup quantization on the critical path.
            if (tid < 2) {
                const int* f = nullptr;
                if (tid == 0 && s > 0) f = &g_flag[flg_base + cell - Tt];
                if (tid == 1 && t > 0) f = &g_flag[flg_base + cell - 1];
                if (f) while (ld_acq(f) < 4) { }
            }
            __syncthreads();

            // Stage parent h_x tiles interleaved (up, left); branchless via g_zero
            const float* up = (s > 0) ? out + (size_t)((layer * Ss + s - 1) * Tt + t) * 2 * (Bb * Hd) : g_zero;
            const float* lf = (t > 0) ? out + (size_t)((layer * Ss + s) * Tt + t - 1) * 2 * (Bb * Hd) : g_zero;
#pragma unroll
            for (int rep = 0; rep < 8; rep++) {
                int idx = rep * 256 + tid;
                int b = idx >> 6, i4 = (idx & 63) << 2;
                float4 u = *reinterpret_cast<const float4*>(&up[b * Hd + i4]);
                float4 l = *reinterpret_cast<const float4*>(&lf[b * Hd + i4]);
                float4* dst = reinterpret_cast<float4*>(&smf[(b * 258 + i4) * 2]);
                dst[0] = make_float4(u.x, l.x, u.y, l.y);
                dst[1] = make_float4(u.z, l.z, u.w, l.w);
            }
            __syncthreads();

            // Recurrent GEMM: acc.lo = up@Ux, acc.hi = left@Uy (all operands in smem).
            // i advances by 2: m loads are LDS.128 covering both i-steps.
            unsigned long long acc[2][4] = {};
#pragma unroll 2
            for (int i = 0; i < 256; i += 2) {
                ulonglong2 m0 = *reinterpret_cast<const ulonglong2*>(m0p + i);
                ulonglong2 m1 = *reinterpret_cast<const ulonglong2*>(m1p + i);
                ulonglong2 wA0 = ws[i * 32 + jq];
                ulonglong2 wB0 = ws[i * 32 + 16 + jq];
                ulonglong2 wA1 = ws[(i + 1) * 32 + jq];
                ulonglong2 wB1 = ws[(i + 1) * 32 + 16 + jq];
                fma2(acc[0][0], m0.x, wA0.x); fma2(acc[0][1], m0.x, wA0.y);
                fma2(acc[0][2], m0.x, wB0.x); fma2(acc[0][3], m0.x, wB0.y);
                fma2(acc[1][0], m1.x, wA0.x); fma2(acc[1][1], m1.x, wA0.y);
                fma2(acc[1][2], m1.x, wB0.x); fma2(acc[1][3], m1.x, wB0.y);
                fma2(acc[0][0], m0.y, wA1.x); fma2(acc[0][1], m0.y, wA1.y);
                fma2(acc[0][2], m0.y, wB1.x); fma2(acc[0][3], m0.y, wB1.y);
                fma2(acc[1][0], m1.y, wA1.x); fma2(acc[1][1], m1.y, wA1.y);
                fma2(acc[1][2], m1.y, wB1.x); fma2(acc[1][3], m1.y, wB1.y);
            }

            // Epilogue
            float* outc = out + (size_t)((layer * Ss + s) * Tt + t) * 2 * (Bb * Hd);
            float bja[4] = {bv.x, bv.y, bv.z, bv.w};
            {
                float tmp0[4], tmp1[4];
#pragma unroll
                for (int jj = 0; jj < 4; jj++) {
                    float2 p0 = unpk(acc[0][jj]);
                    float2 p1 = unpk(acc[1][jj]);
                    tmp0[jj] = p0.x + p0.y + bja[jj];
                    tmp1[jj] = p1.x + p1.y + bja[jj];
                }
                float4 ox0 = make_float4(ftanh(xv0.x + tmp0[0]), ftanh(xv0.y + tmp0[1]),
                                         ftanh(xv0.z + tmp0[2]), ftanh(xv0.w + tmp0[3]));
                float4 oy0 = make_float4(ftanh(yv0.x + tmp0[0]), ftanh(yv0.y + tmp0[1]),
                                         ftanh(yv0.z + tmp0[2]), ftanh(yv0.w + tmp0[3]));
                float4 ox1 = make_float4(ftanh(xv1.x + tmp1[0]), ftanh(xv1.y + tmp1[1]),
                                         ftanh(xv1.z + tmp1[2]), ftanh(xv1.w + tmp1[3]));
                float4 oy1 = make_float4(ftanh(yv1.x + tmp1[0]), ftanh(yv1.y + tmp1[1]),
                                         ftanh(yv1.z + tmp1[2]), ftanh(yv1.w + tmp1[3]));
                *reinterpret_cast<float4*>(&outc[(b0 + 0) * Hd + j0]) = ox0;              // h_x
                *reinterpret_cast<float4*>(&outc[(b0 + 1) * Hd + j0]) = ox1;
                *reinterpret_cast<float4*>(&outc[Bb * Hd + (b0 + 0) * Hd + j0]) = oy0;    // h_y
                *reinterpret_cast<float4*>(&outc[Bb * Hd + (b0 + 1) * Hd + j0]) = oy1;
            }

            // Publish (R8 scheme, measured best): bar orders every thread's STGs,
            // single release per CTA; consumers count to 4.
            __syncthreads();
            if (tid == 0) red_release(&g_flag[flg_base + cell]);
        }
    }
}

extern "C" void kernel_launch(void* const* d_in, const int* in_sizes, int n_in,
                              void* d_out, int out_size) {
    const float* src  = (const float*)d_in[0];   // (48, 32, 256)
    const float* trg  = (const float*)d_in[1];   // (48, 32, 256)
    const float* W    = (const float*)d_in[2];   // (2, 256, 256)
    const float* U    = (const float*)d_in[3];   // (2, 512, 256)
    const float* bias = (const float*)d_in[4];   // (2, 1, 256)
    float* out = (float*)d_out;                  // (2, 48, 48, 2, 32, 256)

    static const int WAVE_SMEM = 131072 + 16 * 258 * 2 * 2 * 4;  // 197120
    cudaFuncSetAttribute(wave_kernel, cudaFuncAttributeMaxDynamicSharedMemorySize, WAVE_SMEM);

    zero_flags<<<9, 512>>>();
    k_interleave<<<512, 256>>>(U);

    // Layer-0 input GEMMs (x and y merged via grid.y; one CTA = all 4 j-blocks)
    pre_kernel<<<dim3(48, 2), 128>>>(src, trg, Bb * Hd, W, 0);

    // Layer-0 wavefront (persistent)
    wave_kernel<<<148, 256, WAVE_SMEM>>>(out, bias, 0);

    // Layer-1 input GEMMs
    pre_kernel<<<dim3(2304, 2), 128>>>(out, out + Bb * Hd, 2 * Bb * Hd, W + Hd * Hd, 1);

    // Layer-1 wavefront (persistent)
    wave_kernel<<<148, 256, WAVE_SMEM>>>(out, bias, 1);
}